// round 12
// baseline (speedup 1.0000x reference)
#include <cuda_runtime.h>
#include <cuda_bf16.h>
#include <cstdint>

// ============================================================================
// QuantizedPatternMatcher — bit-sliced popcount matcher, single persistent
// kernel. R11: cp.async double-buffered tile pipeline in the match phase —
// next tile's smem copy overlaps current tile's compute (no LDG->STS stalls,
// one sync per tile). Encode + R9 inner loop (full unroll, IMAD on fma pipe)
// + keyed-atomicMax argmax all unchanged (proven exact, rel_err 0.0).
//   q(v) = #edges v exceeds (3-bit code); matches[m,p] = #d q_x==q_pat
// Per u32 word: eq = 3xLOP3 -> POPC (alu) -> IMAD (fma).
// Argmax exact: key = cnt*1024 + (1023-p); max == first-max tie-breaking.
// ============================================================================

static constexpr int M_TOTAL = 8192;
static constexpr int P_TOTAL = 1024;
static constexpr int D_DIM   = 512;
static constexpr int NW      = 16;              // u32 words per plane per row
static constexpr int TR      = 64;              // tile rows (both M and P)
static constexpr int MT      = M_TOTAL / TR;    // 128
static constexpr int PT      = P_TOTAL / TR;    // 16
static constexpr int TILE_U32 = NW * 3 * TR;    // 3072 u32 = 12 KB per tile
static constexpr int NTILES  = MT * PT;         // 2048
static constexpr int NCTA    = 592;             // 4/SM x 148 SMs, all resident
static constexpr int ENC_JOBS = (M_TOTAL + P_TOTAL) * D_DIM / 128;  // 36864
static constexpr int SMEM_BYTES = 4 * TILE_U32 * 4;  // 48 KB (A0,A1,B0,B1)

__device__ __align__(16) uint32_t g_Acode[MT * TILE_U32];   // 1.5 MB
__device__ __align__(16) uint32_t g_Bcode[PT * TILE_U32];   // 192 KB
__device__ uint32_t g_key[M_TOTAL];
__device__ unsigned g_bar1, g_bar2, g_fin;
__device__ volatile unsigned g_go1, g_go2;

// NOR-of-xors via guaranteed 3-LOP3 chain.
__device__ __forceinline__ uint32_t eq3(uint32_t a0, uint32_t b0,
                                        uint32_t a1, uint32_t b1,
                                        uint32_t a2, uint32_t b2) {
    uint32_t x, y, z;
    asm("lop3.b32 %0, %1, %2, %3, 0x3C;" : "=r"(x) : "r"(a0), "r"(b0), "r"(0u)); // a^b
    asm("lop3.b32 %0, %1, %2, %3, 0xBE;" : "=r"(y) : "r"(a1), "r"(b1), "r"(x));  // (a^b)|c
    asm("lop3.b32 %0, %1, %2, %3, 0x41;" : "=r"(z) : "r"(a2), "r"(b2), "r"(y));  // ~((a^b)|c)
    return z;
}

// Device-wide barrier across all NCTA resident CTAs (R6/R10-proven pattern).
__device__ __forceinline__ void grid_barrier(unsigned* ctr, volatile unsigned* flag,
                                             int tid) {
    __syncthreads();
    __threadfence();
    if (tid == 0) {
        if (atomicAdd(ctr, 1u) + 1u == (unsigned)NCTA)
            atomicExch((unsigned*)flag, 1u);
        while (*flag == 0u) __nanosleep(64);
    }
    __syncthreads();
    __threadfence();
}

__device__ __forceinline__ void cpa16(uint32_t dst_smem, const void* src) {
    asm volatile("cp.async.cg.shared.global [%0], [%1], 16;"
                 :: "r"(dst_smem), "l"(src));
}

__global__ void __launch_bounds__(256, 4) fused_kernel(
    const float* __restrict__ x, const float* __restrict__ pat,
    const float* __restrict__ edges, float* __restrict__ out, uint32_t one) {
    extern __shared__ __align__(16) uint32_t dsmem[];
    uint32_t* sAbuf[2] = {dsmem,                dsmem + TILE_U32};
    uint32_t* sBbuf[2] = {dsmem + 2 * TILE_U32, dsmem + 3 * TILE_U32};

    const int tid  = threadIdx.x;
    const int cta  = blockIdx.x;
    const int lane = tid & 31;

    // ---- phase 0: zero argmax keys (sliced across CTAs) ----
    for (int i = cta * 256 + tid; i < M_TOTAL; i += NCTA * 256) g_key[i] = 0u;

    // ---- phase 1: encode (R10-proven). Warp-job = (row, 128-dim quarter);
    // float4 load + 12 ballots -> 3 planes x 4 words, fixed dim permutation
    // (identical for A and B, so positional matching is unaffected). ----
    {
        const float e0 = __ldg(edges + 0), e1 = __ldg(edges + 1),
                    e2 = __ldg(edges + 2), e3 = __ldg(edges + 3),
                    e4 = __ldg(edges + 4), e5 = __ldg(edges + 5),
                    e6 = __ldg(edges + 6);
        for (int job = cta * 8 + (tid >> 5); job < ENC_JOBS; job += NCTA * 8) {
            const int r = job >> 2, c = job & 3;
            const float* src;
            uint32_t* dstbase;
            int rr;
            if (r < M_TOTAL) { src = x;   dstbase = g_Acode; rr = r; }
            else             { src = pat; dstbase = g_Bcode; rr = r - M_TOTAL; }

            float4 v = __ldg(reinterpret_cast<const float4*>(
                src + (size_t)rr * D_DIM + c * 128 + lane * 4));
            int q[4];
            q[0] = (v.x > e0) + (v.x > e1) + (v.x > e2) + (v.x > e3) +
                   (v.x > e4) + (v.x > e5) + (v.x > e6);
            q[1] = (v.y > e0) + (v.y > e1) + (v.y > e2) + (v.y > e3) +
                   (v.y > e4) + (v.y > e5) + (v.y > e6);
            q[2] = (v.z > e0) + (v.z > e1) + (v.z > e2) + (v.z > e3) +
                   (v.z > e4) + (v.z > e5) + (v.z > e6);
            q[3] = (v.w > e0) + (v.w > e1) + (v.w > e2) + (v.w > e3) +
                   (v.w > e4) + (v.w > e5) + (v.w > e6);

            uint32_t* base = dstbase + (size_t)(rr >> 6) * TILE_U32 +
                             (rr & 63) + c * 12 * TR;
#pragma unroll
            for (int j = 0; j < 4; j++)
#pragma unroll
                for (int pl = 0; pl < 3; pl++) {
                    unsigned b = __ballot_sync(0xffffffffu, (q[j] >> pl) & 1);
                    const int k = j * 3 + pl;
                    if (lane == k) base[k * TR] = b;
                }
        }
    }

    grid_barrier(&g_bar1, &g_go1, tid);

    // ---- phase 2: match tiles [t0,t1), m-major, cp.async double-buffered ----
    const int t0 = (cta * NTILES) / NCTA;
    const int t1 = ((cta + 1) * NTILES) / NCTA;
    const int tx = tid & 15;
    const int ty = tid >> 4;

    // Each thread copies 3 x 16B per 12KB buffer (768 uint4 / 256 threads).
    auto prefetch = [&](uint32_t* sdst, const uint32_t* gsrc) {
        uint32_t base = (uint32_t)__cvta_generic_to_shared(sdst);
#pragma unroll
        for (int k = 0; k < 3; k++)
            cpa16(base + (uint32_t)(tid + k * 256) * 16,
                  gsrc + (size_t)(tid + k * 256) * 4);
    };

    // Prologue: load first tile's A and B.
    prefetch(sAbuf[0], g_Acode + (size_t)(t0 >> 4) * TILE_U32);
    prefetch(sBbuf[0], g_Bcode + (size_t)(t0 & 15) * TILE_U32);
    asm volatile("cp.async.commit_group;");
    asm volatile("cp.async.wait_group 0;");
    __syncthreads();

    int aBuf = 0, bBuf = 0;
    for (int t = t0; t < t1; t++) {
        const int mt = t >> 4, pt = t & 15;
        const bool haveNext = (t + 1 < t1);
        int nmt = mt;
        if (haveNext) {   // issue next tile's copies; they overlap compute below
            nmt = (t + 1) >> 4;
            const int npt = (t + 1) & 15;
            if (nmt != mt)
                prefetch(sAbuf[aBuf ^ 1], g_Acode + (size_t)nmt * TILE_U32);
            prefetch(sBbuf[bBuf ^ 1], g_Bcode + (size_t)npt * TILE_U32);
            asm volatile("cp.async.commit_group;");
        }

        const uint32_t* sA = sAbuf[aBuf];
        const uint32_t* sB = sBbuf[bBuf];
        const uint4* baseA = reinterpret_cast<const uint4*>(&sA[ty * 4]);
        const uint4* baseB = reinterpret_cast<const uint4*>(&sB[tx * 4]);

        uint32_t acc[4][4];
#pragma unroll
        for (int mi = 0; mi < 4; mi++)
#pragma unroll
            for (int pi = 0; pi < 4; pi++) acc[mi][pi] = 0;

#pragma unroll
        for (int w = 0; w < NW; w++) {
            const uint4 a0 = baseA[(w * 3 + 0) * 16];
            const uint4 a1 = baseA[(w * 3 + 1) * 16];
            const uint4 a2 = baseA[(w * 3 + 2) * 16];
            const uint4 b0 = baseB[(w * 3 + 0) * 16];
            const uint4 b1 = baseB[(w * 3 + 1) * 16];
            const uint4 b2 = baseB[(w * 3 + 2) * 16];

            const uint32_t am0[4] = {a0.x, a0.y, a0.z, a0.w};
            const uint32_t am1[4] = {a1.x, a1.y, a1.z, a1.w};
            const uint32_t am2[4] = {a2.x, a2.y, a2.z, a2.w};
            const uint32_t bp0[4] = {b0.x, b0.y, b0.z, b0.w};
            const uint32_t bp1[4] = {b1.x, b1.y, b1.z, b1.w};
            const uint32_t bp2[4] = {b2.x, b2.y, b2.z, b2.w};

#pragma unroll
            for (int mi = 0; mi < 4; mi++)
#pragma unroll
                for (int pi = 0; pi < 4; pi++) {
                    uint32_t pc = (uint32_t)__popc(
                        eq3(am0[mi], bp0[pi], am1[mi], bp1[pi], am2[mi], bp2[pi]));
                    asm("mad.lo.u32 %0, %1, %2, %0;"
                        : "+r"(acc[mi][pi]) : "r"(pc), "r"(one));
                }
        }

        // key = cnt*1024 + (1023-p): max == first-max (lowest p wins ties).
#pragma unroll
        for (int mi = 0; mi < 4; mi++) {
            uint32_t key = 0;
#pragma unroll
            for (int pi = 0; pi < 4; pi++) {
                uint32_t inv = (uint32_t)(1023 - (pt * TR + tx * 4 + pi));
                uint32_t k;
                asm("mad.lo.u32 %0, %1, %2, %3;"
                    : "=r"(k) : "r"(acc[mi][pi]), "r"(1024u * one), "r"(inv));
                key = key > k ? key : k;
            }
#pragma unroll
            for (int off = 8; off >= 1; off >>= 1) {
                uint32_t o = __shfl_xor_sync(0xffffffffu, key, off);
                key = key > o ? key : o;
            }
            if (tx == 0)
                atomicMax(&g_key[mt * TR + ty * 4 + mi], key);
        }

        if (haveNext) {
            asm volatile("cp.async.wait_group 0;");
            __syncthreads();            // all threads see next tile's smem
            bBuf ^= 1;
            if (nmt != mt) aBuf ^= 1;
        }
    }

    grid_barrier(&g_bar2, &g_go2, tid);

    // ---- phase 3: write outputs (sliced across CTAs) ----
    for (int m = cta * 256 + tid; m < M_TOTAL; m += NCTA * 256) {
        uint32_t best = g_key[m];
        out[m]           = (float)(1023u - (best & 1023u));          // best_patterns
        out[M_TOTAL + m] = (float)(best >> 10) * (1.0f / 512.0f);    // match_scores
    }

    // ---- cleanup: last CTA resets barrier state for the next graph replay ----
    __syncthreads();
    if (tid == 0) {
        if (atomicAdd(&g_fin, 1u) + 1u == (unsigned)NCTA) {
            g_bar1 = 0u; g_bar2 = 0u; g_fin = 0u;
            g_go1 = 0u;  g_go2 = 0u;
            __threadfence();
        }
    }
}

// ---------------------------------------------------------------- launch ----
extern "C" void kernel_launch(void* const* d_in, const int* in_sizes, int n_in,
                              void* d_out, int out_size) {
    const float* x     = (const float*)d_in[0];
    const float* pat   = (const float*)d_in[1];
    const float* edges = (const float*)d_in[2];

    cudaFuncSetAttribute(fused_kernel,
                         cudaFuncAttributeMaxDynamicSharedMemorySize, SMEM_BYTES);
    fused_kernel<<<NCTA, 256, SMEM_BYTES>>>(x, pat, edges, (float*)d_out, 1u);
}

// round 13
// speedup vs baseline: 1.1141x; 1.1141x over previous
#include <cuda_runtime.h>
#include <cuda_bf16.h>
#include <cstdint>

// ============================================================================
// QuantizedPatternMatcher — bit-sliced popcount matcher, single persistent
// kernel. R12 = R10 body (proven 55.8us) + two fixes:
//  (1) NCTA=444 (3 CTAs/SM): tile imbalance 15.6% -> 8.4%
//  (2) encode prefetch: next LDG.128 issued before current job's processing
//   q(v) = #edges v exceeds (3-bit code); matches[m,p] = #d q_x==q_pat
// Per u32 word: eq = 3xLOP3 -> POPC (alu floor) -> IMAD (fma pipe).
// Argmax exact: key = cnt*1024 + (1023-p); max == first-max tie-breaking.
// ============================================================================

static constexpr int M_TOTAL = 8192;
static constexpr int P_TOTAL = 1024;
static constexpr int D_DIM   = 512;
static constexpr int NW      = 16;              // u32 words per plane per row
static constexpr int TR      = 64;              // tile rows (both M and P)
static constexpr int MT      = M_TOTAL / TR;    // 128
static constexpr int PT      = P_TOTAL / TR;    // 16
static constexpr int TILE_U32 = NW * 3 * TR;    // 3072 u32 = 12 KB per tile
static constexpr int NTILES  = MT * PT;         // 2048
static constexpr int NCTA    = 444;             // 3/SM x 148 SMs, all resident
static constexpr int ENC_JOBS = (M_TOTAL + P_TOTAL) * D_DIM / 128;  // 36864

__device__ __align__(16) uint32_t g_Acode[MT * TILE_U32];   // 1.5 MB
__device__ __align__(16) uint32_t g_Bcode[PT * TILE_U32];   // 192 KB
__device__ uint32_t g_key[M_TOTAL];
__device__ unsigned g_bar1, g_bar2, g_fin;
__device__ volatile unsigned g_go1, g_go2;

// NOR-of-xors via guaranteed 3-LOP3 chain.
__device__ __forceinline__ uint32_t eq3(uint32_t a0, uint32_t b0,
                                        uint32_t a1, uint32_t b1,
                                        uint32_t a2, uint32_t b2) {
    uint32_t x, y, z;
    asm("lop3.b32 %0, %1, %2, %3, 0x3C;" : "=r"(x) : "r"(a0), "r"(b0), "r"(0u)); // a^b
    asm("lop3.b32 %0, %1, %2, %3, 0xBE;" : "=r"(y) : "r"(a1), "r"(b1), "r"(x));  // (a^b)|c
    asm("lop3.b32 %0, %1, %2, %3, 0x41;" : "=r"(z) : "r"(a2), "r"(b2), "r"(y));  // ~((a^b)|c)
    return z;
}

// Device-wide barrier across all NCTA resident CTAs (R6/R10-proven pattern).
__device__ __forceinline__ void grid_barrier(unsigned* ctr, volatile unsigned* flag,
                                             int tid) {
    __syncthreads();
    __threadfence();
    if (tid == 0) {
        if (atomicAdd(ctr, 1u) + 1u == (unsigned)NCTA)
            atomicExch((unsigned*)flag, 1u);
        while (*flag == 0u) __nanosleep(64);
    }
    __syncthreads();
    __threadfence();
}

__global__ void __launch_bounds__(256, 3) fused_kernel(
    const float* __restrict__ x, const float* __restrict__ pat,
    const float* __restrict__ edges, float* __restrict__ out, uint32_t one) {
    __shared__ uint32_t sA[TILE_U32];
    __shared__ uint32_t sB[TILE_U32];

    const int tid  = threadIdx.x;
    const int cta  = blockIdx.x;
    const int lane = tid & 31;

    // ---- phase 0: zero argmax keys (sliced across CTAs) ----
    for (int i = cta * 256 + tid; i < M_TOTAL; i += NCTA * 256) g_key[i] = 0u;

    // ---- phase 1: encode with prefetch. Warp-job = (row, 128-dim quarter);
    // float4 load + 12 ballots -> 3 planes x 4 words, fixed dim permutation
    // (identical for A and B, so positional matching is unaffected). The next
    // job's LDG.128 is issued before processing the current one. ----
    {
        const float e0 = __ldg(edges + 0), e1 = __ldg(edges + 1),
                    e2 = __ldg(edges + 2), e3 = __ldg(edges + 3),
                    e4 = __ldg(edges + 4), e5 = __ldg(edges + 5),
                    e6 = __ldg(edges + 6);
        const int STRIDE = NCTA * 8;

        auto job_src = [&](int job) -> const float4* {
            const int r = job >> 2, c = job & 3;
            const float* s = (r < M_TOTAL) ? x : pat;
            const int rr   = (r < M_TOTAL) ? r : r - M_TOTAL;
            return reinterpret_cast<const float4*>(
                s + (size_t)rr * D_DIM + c * 128 + lane * 4);
        };

        int job = cta * 8 + (tid >> 5);
        float4 v;
        if (job < ENC_JOBS) v = __ldg(job_src(job));
        while (job < ENC_JOBS) {
            const int jnext = job + STRIDE;
            float4 vn;
            if (jnext < ENC_JOBS) vn = __ldg(job_src(jnext));   // prefetch

            const int r = job >> 2, c = job & 3;
            uint32_t* dstbase = (r < M_TOTAL) ? g_Acode : g_Bcode;
            const int rr      = (r < M_TOTAL) ? r : r - M_TOTAL;

            int q[4];
            q[0] = (v.x > e0) + (v.x > e1) + (v.x > e2) + (v.x > e3) +
                   (v.x > e4) + (v.x > e5) + (v.x > e6);
            q[1] = (v.y > e0) + (v.y > e1) + (v.y > e2) + (v.y > e3) +
                   (v.y > e4) + (v.y > e5) + (v.y > e6);
            q[2] = (v.z > e0) + (v.z > e1) + (v.z > e2) + (v.z > e3) +
                   (v.z > e4) + (v.z > e5) + (v.z > e6);
            q[3] = (v.w > e0) + (v.w > e1) + (v.w > e2) + (v.w > e3) +
                   (v.w > e4) + (v.w > e5) + (v.w > e6);

            uint32_t* base = dstbase + (size_t)(rr >> 6) * TILE_U32 +
                             (rr & 63) + c * 12 * TR;
#pragma unroll
            for (int j = 0; j < 4; j++)
#pragma unroll
                for (int pl = 0; pl < 3; pl++) {
                    unsigned b = __ballot_sync(0xffffffffu, (q[j] >> pl) & 1);
                    const int k = j * 3 + pl;
                    if (lane == k) base[k * TR] = b;
                }

            v = vn;
            job = jnext;
        }
    }

    grid_barrier(&g_bar1, &g_go1, tid);

    // ---- phase 2: match tiles [t0,t1), m-major so sA reused across pt ----
    const int t0 = (cta * NTILES) / NCTA;
    const int t1 = ((cta + 1) * NTILES) / NCTA;
    const int tx = tid & 15;
    const int ty = tid >> 4;
    int cur_mt = -1;

    for (int t = t0; t < t1; t++) {
        const int mt = t >> 4, pt = t & 15;

        __syncthreads();   // previous tile's compute done before smem overwrite
        if (mt != cur_mt) {   // uniform branch
            const uint4* gA = reinterpret_cast<const uint4*>(g_Acode + (size_t)mt * TILE_U32);
            uint4* s4A = reinterpret_cast<uint4*>(sA);
#pragma unroll
            for (int i = 0; i < TILE_U32 / 4; i += 256) s4A[i + tid] = gA[i + tid];
            cur_mt = mt;
        }
        {
            const uint4* gB = reinterpret_cast<const uint4*>(g_Bcode + (size_t)pt * TILE_U32);
            uint4* s4B = reinterpret_cast<uint4*>(sB);
#pragma unroll
            for (int i = 0; i < TILE_U32 / 4; i += 256) s4B[i + tid] = gB[i + tid];
        }
        __syncthreads();

        // Base pointers; every load below is [base + compile-time-imm].
        const uint4* baseA = reinterpret_cast<const uint4*>(&sA[ty * 4]);
        const uint4* baseB = reinterpret_cast<const uint4*>(&sB[tx * 4]);

        uint32_t acc[4][4];
#pragma unroll
        for (int mi = 0; mi < 4; mi++)
#pragma unroll
            for (int pi = 0; pi < 4; pi++) acc[mi][pi] = 0;

#pragma unroll
        for (int w = 0; w < NW; w++) {
            const uint4 a0 = baseA[(w * 3 + 0) * 16];
            const uint4 a1 = baseA[(w * 3 + 1) * 16];
            const uint4 a2 = baseA[(w * 3 + 2) * 16];
            const uint4 b0 = baseB[(w * 3 + 0) * 16];
            const uint4 b1 = baseB[(w * 3 + 1) * 16];
            const uint4 b2 = baseB[(w * 3 + 2) * 16];

            const uint32_t am0[4] = {a0.x, a0.y, a0.z, a0.w};
            const uint32_t am1[4] = {a1.x, a1.y, a1.z, a1.w};
            const uint32_t am2[4] = {a2.x, a2.y, a2.z, a2.w};
            const uint32_t bp0[4] = {b0.x, b0.y, b0.z, b0.w};
            const uint32_t bp1[4] = {b1.x, b1.y, b1.z, b1.w};
            const uint32_t bp2[4] = {b2.x, b2.y, b2.z, b2.w};

#pragma unroll
            for (int mi = 0; mi < 4; mi++)
#pragma unroll
                for (int pi = 0; pi < 4; pi++) {
                    uint32_t pc = (uint32_t)__popc(
                        eq3(am0[mi], bp0[pi], am1[mi], bp1[pi], am2[mi], bp2[pi]));
                    asm("mad.lo.u32 %0, %1, %2, %0;"
                        : "+r"(acc[mi][pi]) : "r"(pc), "r"(one));
                }
        }

        // key = cnt*1024 + (1023-p): max == first-max (lowest p wins ties).
#pragma unroll
        for (int mi = 0; mi < 4; mi++) {
            uint32_t key = 0;
#pragma unroll
            for (int pi = 0; pi < 4; pi++) {
                uint32_t inv = (uint32_t)(1023 - (pt * TR + tx * 4 + pi));
                uint32_t k;
                asm("mad.lo.u32 %0, %1, %2, %3;"
                    : "=r"(k) : "r"(acc[mi][pi]), "r"(1024u * one), "r"(inv));
                key = key > k ? key : k;
            }
#pragma unroll
            for (int off = 8; off >= 1; off >>= 1) {
                uint32_t o = __shfl_xor_sync(0xffffffffu, key, off);
                key = key > o ? key : o;
            }
            if (tx == 0)
                atomicMax(&g_key[mt * TR + ty * 4 + mi], key);
        }
    }

    grid_barrier(&g_bar2, &g_go2, tid);

    // ---- phase 3: write outputs (sliced across CTAs) ----
    for (int m = cta * 256 + tid; m < M_TOTAL; m += NCTA * 256) {
        uint32_t best = g_key[m];
        out[m]           = (float)(1023u - (best & 1023u));          // best_patterns
        out[M_TOTAL + m] = (float)(best >> 10) * (1.0f / 512.0f);    // match_scores
    }

    // ---- cleanup: last CTA resets barrier state for the next graph replay ----
    __syncthreads();
    if (tid == 0) {
        if (atomicAdd(&g_fin, 1u) + 1u == (unsigned)NCTA) {
            g_bar1 = 0u; g_bar2 = 0u; g_fin = 0u;
            g_go1 = 0u;  g_go2 = 0u;
            __threadfence();
        }
    }
}

// ---------------------------------------------------------------- launch ----
extern "C" void kernel_launch(void* const* d_in, const int* in_sizes, int n_in,
                              void* d_out, int out_size) {
    const float* x     = (const float*)d_in[0];
    const float* pat   = (const float*)d_in[1];
    const float* edges = (const float*)d_in[2];

    fused_kernel<<<NCTA, 256>>>(x, pat, edges, (float*)d_out, 1u);
}